// round 1
// baseline (speedup 1.0000x reference)
#include <cuda_runtime.h>
#include <cstdint>

// Problem constants (validated against in_sizes at launch).
#define N_FEAT 32
#define N_COLS 128          // 4 relations * 32 output features
#define MAX_NODES 524288
#define TILE_NODES 64

// Scratch (no cudaMalloc allowed): xt (N x 128), two agg buffers (N x 32).
__device__ float g_xt[(size_t)MAX_NODES * N_COLS];    // 256 MB
__device__ float g_agg1[(size_t)MAX_NODES * N_FEAT];  // 64 MB
__device__ float g_agg2[(size_t)MAX_NODES * N_FEAT];  // 64 MB

// ---------------------------------------------------------------------------
// Transform: xt[n][r*32+o] = sum_d act(xin[n][d]) * W[r][d][o]
// act = relu(v + b[d]) when PRE_ACT (layer 2 input), identity otherwise.
// Block: 256 threads = 64 column-pairs x 4 node slots; tile = 64 nodes.
// W columns held in registers (float2 w[32] = 64 regs), x tile in smem.
// ---------------------------------------------------------------------------
template<bool PRE_ACT>
__global__ void __launch_bounds__(256) transform_k(
    const float* __restrict__ xin, const float* __restrict__ W,
    const float* __restrict__ b, float* __restrict__ xt)
{
    __shared__ float4 xs4[TILE_NODES * 8];  // 64 nodes * 32 floats = 8 KB

    const int tid  = threadIdx.x;
    const int cp   = tid & 63;     // column pair -> cols 2cp, 2cp+1
    const int slot = tid >> 6;     // 0..3
    const int base = blockIdx.x * TILE_NODES;

    const int col0 = 2 * cp;
    const int r    = col0 >> 5;    // relation
    const int o    = col0 & 31;    // output feature within relation

    // Load this thread's two W columns into registers.
    // W layout: W[r*1024 + d*32 + o]; pair (o, o+1) is contiguous & 8B aligned.
    float2 w[32];
    #pragma unroll
    for (int k = 0; k < 32; k++) {
        w[k] = *reinterpret_cast<const float2*>(W + r * 1024 + k * 32 + o);
    }

    // Cooperatively load x tile (apply bias+relu for layer-2 input).
    const float4* xin4 = reinterpret_cast<const float4*>(xin + (size_t)base * N_FEAT);
    #pragma unroll
    for (int i = tid; i < TILE_NODES * 8; i += 256) {
        float4 v = xin4[i];
        if (PRE_ACT) {
            const int k = (i & 7) * 4;
            v.x = fmaxf(v.x + b[k + 0], 0.f);
            v.y = fmaxf(v.y + b[k + 1], 0.f);
            v.z = fmaxf(v.z + b[k + 2], 0.f);
            v.w = fmaxf(v.w + b[k + 3], 0.f);
        }
        xs4[i] = v;
    }
    __syncthreads();

    // Each thread: 16 nodes x 2 columns.
    for (int nn = slot; nn < TILE_NODES; nn += 4) {
        float accx = 0.f, accy = 0.f;
        const float4* xr = &xs4[nn * 8];
        #pragma unroll
        for (int kk = 0; kk < 8; kk++) {
            const float4 xv = xr[kk];        // LDS.128 broadcast (uniform addr in warp)
            const int k = kk * 4;
            accx = fmaf(xv.x, w[k + 0].x, accx); accy = fmaf(xv.x, w[k + 0].y, accy);
            accx = fmaf(xv.y, w[k + 1].x, accx); accy = fmaf(xv.y, w[k + 1].y, accy);
            accx = fmaf(xv.z, w[k + 2].x, accx); accy = fmaf(xv.z, w[k + 2].y, accy);
            accx = fmaf(xv.w, w[k + 3].x, accx); accy = fmaf(xv.w, w[k + 3].y, accy);
        }
        float2 acc = make_float2(accx, accy);
        *reinterpret_cast<float2*>(xt + (size_t)(base + nn) * N_COLS + col0) = acc;
    }
}

// ---------------------------------------------------------------------------
// Zero fill (graph-safe, avoids memset/symbol games).
// ---------------------------------------------------------------------------
__global__ void zero_k(float4* __restrict__ p, int n4)
{
    const int i = blockIdx.x * blockDim.x + threadIdx.x;
    if (i < n4) p[i] = make_float4(0.f, 0.f, 0.f, 0.f);
}

// ---------------------------------------------------------------------------
// Edge scatter: agg[dst] += xt[src, etype*32 : etype*32+32]
// 8 lanes per edge, each moves one float4 via vector RED (sm_90+).
// ---------------------------------------------------------------------------
__global__ void __launch_bounds__(256) scatter_k(
    const float* __restrict__ xt, const int* __restrict__ src,
    const int* __restrict__ dst, const int* __restrict__ et,
    float* __restrict__ agg, int nedges)
{
    const int t = blockIdx.x * blockDim.x + threadIdx.x;
    const int e = t >> 3;
    if (e >= nedges) return;
    const int q = t & 7;

    const int s = __ldg(src + e);
    const int d = __ldg(dst + e);
    const int r = __ldg(et  + e);

    const float4 v = *reinterpret_cast<const float4*>(
        xt + (size_t)s * N_COLS + r * N_FEAT + q * 4);

    float* ap = agg + (size_t)d * N_FEAT + q * 4;
    asm volatile("red.global.add.v4.f32 [%0], {%1, %2, %3, %4};"
                 :: "l"(ap), "f"(v.x), "f"(v.y), "f"(v.z), "f"(v.w)
                 : "memory");
}

// ---------------------------------------------------------------------------
// Pool: out[g][c] = mean_{i<32} relu(agg2[g*32+i][c] + b[c]);  one warp per group.
// ---------------------------------------------------------------------------
__global__ void __launch_bounds__(256) pool_k(
    const float* __restrict__ agg, const float* __restrict__ b,
    float* __restrict__ out, int nnodes)
{
    const int t = blockIdx.x * blockDim.x + threadIdx.x;
    if (t >= nnodes) return;           // nnodes == ngroups * 32 outputs
    const int c = t & 31;
    const int g = t >> 5;
    const float bc = b[c];
    const float* p = agg + (size_t)g * 32 * N_FEAT + c;
    float s = 0.f;
    #pragma unroll
    for (int i = 0; i < 32; i++) {
        s += fmaxf(p[i * N_FEAT] + bc, 0.f);
    }
    out[t] = s * (1.0f / 32.0f);
}

// ---------------------------------------------------------------------------
// Launch: layer1 (transform -> zero -> scatter), layer2 (same, with fused
// bias+relu on input), then block-mean pool (bias+relu fused).
// ---------------------------------------------------------------------------
extern "C" void kernel_launch(void* const* d_in, const int* in_sizes, int n_in,
                              void* d_out, int out_size)
{
    const float* x   = (const float*)d_in[0];
    const int*   src = (const int*)  d_in[1];
    const int*   dst = (const int*)  d_in[2];
    const int*   et  = (const int*)  d_in[3];
    const float* W   = (const float*)d_in[4];
    const float* b   = (const float*)d_in[5];

    const int nnodes = in_sizes[0] / N_FEAT;
    const int nedges = in_sizes[1];

    float *xt, *agg1, *agg2;
    cudaGetSymbolAddress((void**)&xt,   g_xt);
    cudaGetSymbolAddress((void**)&agg1, g_agg1);
    cudaGetSymbolAddress((void**)&agg2, g_agg2);

    const int tf_blocks = nnodes / TILE_NODES;
    const int n4        = nnodes * N_FEAT / 4;
    const int z_blocks  = (n4 + 255) / 256;
    const int sc_blocks = (nedges * 8 + 255) / 256;

    // Layer 1
    transform_k<false><<<tf_blocks, 256>>>(x, W, b, xt);
    zero_k<<<z_blocks, 256>>>((float4*)agg1, n4);
    scatter_k<<<sc_blocks, 256>>>(xt, src, dst, et, agg1, nedges);

    // Layer 2 (input = relu(agg1 + b), fused into transform)
    transform_k<true><<<tf_blocks, 256>>>(agg1, W, b, xt);
    zero_k<<<z_blocks, 256>>>((float4*)agg2, n4);
    scatter_k<<<sc_blocks, 256>>>(xt, src, dst, et, agg2, nedges);

    // Pool (bias+relu fused), out = (nnodes/32, 32) floats
    pool_k<<<(nnodes + 255) / 256, 256>>>(agg2, b, (float*)d_out, nnodes);
    (void)n_in; (void)out_size;
}

// round 2
// speedup vs baseline: 1.0056x; 1.0056x over previous
#include <cuda_runtime.h>
#include <cuda_fp16.h>
#include <cstdint>

#define N_FEAT 32
#define N_COLS 128          // 4 relations * 32 output features
#define MAX_NODES 524288
#define TN 128              // nodes per transform block

// Scratch: xt now fp16 (128 MB), two fp32 agg buffers (64 MB each).
__device__ __half g_xt[(size_t)MAX_NODES * N_COLS];
__device__ float  g_agg1[(size_t)MAX_NODES * N_FEAT];
__device__ float  g_agg2[(size_t)MAX_NODES * N_FEAT];

// ---------------------------------------------------------------------------
// Transform: xt[n][r*32+o] = sum_d act(xin[n][d]) * W[r][d][o], output fp16.
// GEMM tiling: block = 128 nodes x 128 cols, 256 threads, each thread owns an
// 8x8 accumulator tile. x tile transposed (k-major) in smem; W (32x128) in
// smem. Inner loop: 4 LDS.128 per 64 FFMA -> fma-pipe bound.
// act = relu(v + b[d]) when PRE_ACT (layer-2 input), identity otherwise.
// ---------------------------------------------------------------------------
template<bool PRE_ACT>
__global__ void __launch_bounds__(256) transform_k(
    const float* __restrict__ xin, const float* __restrict__ W,
    const float* __restrict__ b, __half* __restrict__ xt)
{
    __shared__ float xs[N_FEAT][TN];      // 16 KB, k-major (transposed)
    __shared__ float ws[N_FEAT][N_COLS];  // 16 KB, d-major, col = r*32+o

    const int tid  = threadIdx.x;
    const int base = blockIdx.x * TN;

    // Fill W smem: Wcat[d][r*32+o] = W[r][d][o]. 1024 float4 loads.
    for (int f = tid; f < 1024; f += 256) {
        float4 v = reinterpret_cast<const float4*>(W)[f];
        const int r = f >> 8, d = (f >> 3) & 31, o4 = f & 7;
        *reinterpret_cast<float4*>(&ws[d][r * 32 + o4 * 4]) = v;
    }

    // Fill x tile transposed (apply bias+relu for layer-2 input).
    const float4* xin4 = reinterpret_cast<const float4*>(xin + (size_t)base * N_FEAT);
    for (int f = tid; f < TN * 8; f += 256) {
        float4 v = xin4[f];
        const int i = f >> 3, kq = f & 7;
        if (PRE_ACT) {
            v.x = fmaxf(v.x + __ldg(b + kq * 4 + 0), 0.f);
            v.y = fmaxf(v.y + __ldg(b + kq * 4 + 1), 0.f);
            v.z = fmaxf(v.z + __ldg(b + kq * 4 + 2), 0.f);
            v.w = fmaxf(v.w + __ldg(b + kq * 4 + 3), 0.f);
        }
        xs[kq * 4 + 0][i] = v.x;
        xs[kq * 4 + 1][i] = v.y;
        xs[kq * 4 + 2][i] = v.z;
        xs[kq * 4 + 3][i] = v.w;
    }
    __syncthreads();

    const int ng = tid >> 4;   // node group 0..15 -> nodes ng*8 .. +7
    const int cg = tid & 15;   // col group 0..15 -> cols cg*8 .. +7

    float acc[8][8];
    #pragma unroll
    for (int i = 0; i < 8; i++)
        #pragma unroll
        for (int j = 0; j < 8; j++) acc[i][j] = 0.f;

    #pragma unroll 4
    for (int k = 0; k < N_FEAT; k++) {
        const float4 xa = *reinterpret_cast<const float4*>(&xs[k][ng * 8]);
        const float4 xb = *reinterpret_cast<const float4*>(&xs[k][ng * 8 + 4]);
        const float4 wa = *reinterpret_cast<const float4*>(&ws[k][cg * 8]);
        const float4 wb = *reinterpret_cast<const float4*>(&ws[k][cg * 8 + 4]);
        const float xv[8] = {xa.x, xa.y, xa.z, xa.w, xb.x, xb.y, xb.z, xb.w};
        const float wv[8] = {wa.x, wa.y, wa.z, wa.w, wb.x, wb.y, wb.z, wb.w};
        #pragma unroll
        for (int i = 0; i < 8; i++)
            #pragma unroll
            for (int j = 0; j < 8; j++)
                acc[i][j] = fmaf(xv[i], wv[j], acc[i][j]);
    }

    // Epilogue: convert to fp16, one STG.128 (8 cols) per node.
    #pragma unroll
    for (int i = 0; i < 8; i++) {
        const size_t node = (size_t)(base + ng * 8 + i);
        __half2 h[4];
        #pragma unroll
        for (int j = 0; j < 4; j++)
            h[j] = __floats2half2_rn(acc[i][2 * j], acc[i][2 * j + 1]);
        *reinterpret_cast<uint4*>(xt + node * N_COLS + cg * 8) =
            *reinterpret_cast<uint4*>(h);
    }
}

// ---------------------------------------------------------------------------
// Zero fill.
// ---------------------------------------------------------------------------
__global__ void zero_k(float4* __restrict__ p, int n4)
{
    const int i = blockIdx.x * blockDim.x + threadIdx.x;
    if (i < n4) p[i] = make_float4(0.f, 0.f, 0.f, 0.f);
}

// ---------------------------------------------------------------------------
// Edge scatter: agg[dst] += fp32(xt_fp16[src, etype*32 : +32]).
// 4 lanes per edge; each lane gathers 16B (8 halfs), converts, issues two
// red.global.add.v4.f32.
// ---------------------------------------------------------------------------
__global__ void __launch_bounds__(256) scatter_k(
    const __half* __restrict__ xt, const int* __restrict__ src,
    const int* __restrict__ dst, const int* __restrict__ et,
    float* __restrict__ agg, int nedges)
{
    const int t = blockIdx.x * blockDim.x + threadIdx.x;
    const int e = t >> 2;
    if (e >= nedges) return;
    const int q = t & 3;

    const int s = __ldg(src + e);
    const int d = __ldg(dst + e);
    const int r = __ldg(et  + e);

    const uint4 p = *reinterpret_cast<const uint4*>(
        xt + (size_t)s * N_COLS + r * N_FEAT + q * 8);
    const __half2* hp = reinterpret_cast<const __half2*>(&p);
    const float2 f0 = __half22float2(hp[0]);
    const float2 f1 = __half22float2(hp[1]);
    const float2 f2 = __half22float2(hp[2]);
    const float2 f3 = __half22float2(hp[3]);

    float* ap = agg + (size_t)d * N_FEAT + q * 8;
    asm volatile("red.global.add.v4.f32 [%0], {%1, %2, %3, %4};"
                 :: "l"(ap), "f"(f0.x), "f"(f0.y), "f"(f1.x), "f"(f1.y)
                 : "memory");
    asm volatile("red.global.add.v4.f32 [%0], {%1, %2, %3, %4};"
                 :: "l"(ap + 4), "f"(f2.x), "f"(f2.y), "f"(f3.x), "f"(f3.y)
                 : "memory");
}

// ---------------------------------------------------------------------------
// Pool: out[g][c] = mean_{i<32} relu(agg2[g*32+i][c] + b[c]).
// ---------------------------------------------------------------------------
__global__ void __launch_bounds__(256) pool_k(
    const float* __restrict__ agg, const float* __restrict__ b,
    float* __restrict__ out, int nnodes)
{
    const int t = blockIdx.x * blockDim.x + threadIdx.x;
    if (t >= nnodes) return;
    const int c = t & 31;
    const int g = t >> 5;
    const float bc = __ldg(b + c);
    const float* p = agg + (size_t)g * 32 * N_FEAT + c;
    float s = 0.f;
    #pragma unroll
    for (int i = 0; i < 32; i++)
        s += fmaxf(p[i * N_FEAT] + bc, 0.f);
    out[t] = s * (1.0f / 32.0f);
}

// ---------------------------------------------------------------------------
extern "C" void kernel_launch(void* const* d_in, const int* in_sizes, int n_in,
                              void* d_out, int out_size)
{
    const float* x   = (const float*)d_in[0];
    const int*   src = (const int*)  d_in[1];
    const int*   dst = (const int*)  d_in[2];
    const int*   et  = (const int*)  d_in[3];
    const float* W   = (const float*)d_in[4];
    const float* b   = (const float*)d_in[5];

    const int nnodes = in_sizes[0] / N_FEAT;
    const int nedges = in_sizes[1];

    __half *xt; float *agg1, *agg2;
    cudaGetSymbolAddress((void**)&xt,   g_xt);
    cudaGetSymbolAddress((void**)&agg1, g_agg1);
    cudaGetSymbolAddress((void**)&agg2, g_agg2);

    const int tf_blocks = nnodes / TN;
    const int n4        = nnodes * N_FEAT / 4;
    const int z_blocks  = (n4 + 255) / 256;
    const int sc_blocks = (nedges * 4 + 255) / 256;

    // Layer 1
    transform_k<false><<<tf_blocks, 256>>>(x, W, b, xt);
    zero_k<<<z_blocks, 256>>>((float4*)agg1, n4);
    scatter_k<<<sc_blocks, 256>>>(xt, src, dst, et, agg1, nedges);

    // Layer 2 (input = relu(agg1 + b), fused into transform)
    transform_k<true><<<tf_blocks, 256>>>(agg1, W, b, xt);
    zero_k<<<z_blocks, 256>>>((float4*)agg2, n4);
    scatter_k<<<sc_blocks, 256>>>(xt, src, dst, et, agg2, nedges);

    // Pool (bias+relu fused)
    pool_k<<<(nnodes + 255) / 256, 256>>>(agg2, b, (float*)d_out, nnodes);
    (void)n_in; (void)out_size;
}

// round 4
// speedup vs baseline: 2.1073x; 2.0956x over previous
#include <cuda_runtime.h>
#include <cuda_fp16.h>
#include <cstdint>

#define N_FEAT 32
#define N_COLS 128          // 4 relations * 32 output features
#define MAX_NODES 524288
#define TN 128              // nodes per transform block

#define XH_STRIDE 40        // halfs per x-tile row (padded, conflict-free ldmatrix)
#define WH_STRIDE 136       // halfs per W row (padded)
#define ST_STRIDE 136       // halfs per staging row (16B-aligned rows: 272B)

// Scratch: xt fp16 (128 MB), agg buffers fp16 (32 MB each).
__device__ __half g_xt[(size_t)MAX_NODES * N_COLS];
__device__ __half g_agg1[(size_t)MAX_NODES * N_FEAT];
__device__ __half g_agg2[(size_t)MAX_NODES * N_FEAT];

// ---------------------------------------------------------------------------
// Tensor-core transform: xt[n][r*32+o] = sum_d act(in[n][d]) * W[r][d][o]
// Block = 128 nodes x 128 cols, 8 warps; warp w owns rows w*16..+15 (M=16),
// sweeps N in 16 tiles of 8, K=32 in 2 steps of 16.
// A (x tile, fp16) via ldmatrix.x4; B (Wcat, fp16) via ldmatrix.x2.trans.
// fp32 accumulate; epilogue staged in smem for coalesced uint4 stores.
// PRE_ACT: in is fp16 agg, apply relu(v + b[d]) first. Else: in is fp32 x.
// ---------------------------------------------------------------------------
template<bool PRE_ACT>
__global__ void __launch_bounds__(256) transform_k(
    const void* __restrict__ xin_, const float* __restrict__ W,
    const float* __restrict__ b, __half* __restrict__ xt)
{
    __shared__ __align__(16) unsigned char sm[TN * ST_STRIDE * 2]; // 34816 B
    __half* xh    = reinterpret_cast<__half*>(sm);           // [128][XH_STRIDE]
    __half* wh    = reinterpret_cast<__half*>(sm + 10240);   // [32][WH_STRIDE]
    __half* stage = reinterpret_cast<__half*>(sm);           // [128][ST_STRIDE]

    const int tid  = threadIdx.x;
    const int base = blockIdx.x * TN;

    // ---- Fill W smem: wh[d][r*32+o] = half(W[r][d][o]) ----
    for (int f = tid; f < 1024; f += 256) {
        const float4 v = reinterpret_cast<const float4*>(W)[f];
        const int r = f >> 8, d = (f >> 3) & 31, o4 = f & 7;
        __half* p = &wh[d * WH_STRIDE + r * 32 + o4 * 4];
        p[0] = __float2half_rn(v.x); p[1] = __float2half_rn(v.y);
        p[2] = __float2half_rn(v.z); p[3] = __float2half_rn(v.w);
    }

    // ---- Fill x tile (convert to fp16; bias+relu for layer-2 input) ----
    if (PRE_ACT) {
        const __half* xin = reinterpret_cast<const __half*>(xin_);
        for (int f = tid; f < TN * 4; f += 256) {       // 8 halfs per iter
            const int i = f >> 2, kq = f & 3;
            const uint4 pk = *reinterpret_cast<const uint4*>(
                xin + (size_t)(base + i) * N_FEAT + kq * 8);
            const __half2* hp = reinterpret_cast<const __half2*>(&pk);
            const float4 b0 = __ldg(reinterpret_cast<const float4*>(b + kq * 8));
            const float4 b1 = __ldg(reinterpret_cast<const float4*>(b + kq * 8 + 4));
            const float bb[8] = {b0.x, b0.y, b0.z, b0.w, b1.x, b1.y, b1.z, b1.w};
            __half* d = &xh[i * XH_STRIDE + kq * 8];
            #pragma unroll
            for (int j = 0; j < 4; j++) {
                float2 fv = __half22float2(hp[j]);
                fv.x = fmaxf(fv.x + bb[j * 2 + 0], 0.f);
                fv.y = fmaxf(fv.y + bb[j * 2 + 1], 0.f);
                *reinterpret_cast<__half2*>(d + j * 2) = __floats2half2_rn(fv.x, fv.y);
            }
        }
    } else {
        const float4* xin4 = reinterpret_cast<const float4*>(
            reinterpret_cast<const float*>(xin_) + (size_t)base * N_FEAT);
        for (int f = tid; f < TN * 8; f += 256) {       // 4 floats per iter
            const float4 v = xin4[f];
            const int i = f >> 3, kq = f & 7;
            __half* d = &xh[i * XH_STRIDE + kq * 4];
            *reinterpret_cast<__half2*>(d)     = __floats2half2_rn(v.x, v.y);
            *reinterpret_cast<__half2*>(d + 2) = __floats2half2_rn(v.z, v.w);
        }
    }
    __syncthreads();

    // ---- MMA ----
    const int w    = tid >> 5;
    const int lane = tid & 31;
    const int m0   = w * 16;

    uint32_t a[2][4];
    #pragma unroll
    for (int s = 0; s < 2; s++) {
        const int row = m0 + (lane & 15);
        const int col = s * 16 + ((lane >> 4) << 3);
        const uint32_t addr =
            (uint32_t)__cvta_generic_to_shared(&xh[row * XH_STRIDE + col]);
        asm volatile("ldmatrix.sync.aligned.m8n8.x4.shared.b16 {%0,%1,%2,%3}, [%4];"
                     : "=r"(a[s][0]), "=r"(a[s][1]), "=r"(a[s][2]), "=r"(a[s][3])
                     : "r"(addr));
    }

    float acc[16][4];
    #pragma unroll
    for (int j = 0; j < 16; j++)
        #pragma unroll
        for (int q = 0; q < 4; q++) acc[j][q] = 0.f;

    #pragma unroll
    for (int j = 0; j < 16; j++) {
        #pragma unroll
        for (int s = 0; s < 2; s++) {
            const int krow = s * 16 + (lane & 15);
            const uint32_t baddr =
                (uint32_t)__cvta_generic_to_shared(&wh[krow * WH_STRIDE + j * 8]);
            uint32_t b0, b1;
            asm volatile("ldmatrix.sync.aligned.m8n8.x2.trans.shared.b16 {%0,%1}, [%2];"
                         : "=r"(b0), "=r"(b1) : "r"(baddr));
            asm volatile(
                "mma.sync.aligned.m16n8k16.row.col.f32.f16.f16.f32 "
                "{%0,%1,%2,%3}, {%4,%5,%6,%7}, {%8,%9}, {%0,%1,%2,%3};"
                : "+f"(acc[j][0]), "+f"(acc[j][1]), "+f"(acc[j][2]), "+f"(acc[j][3])
                : "r"(a[s][0]), "r"(a[s][1]), "r"(a[s][2]), "r"(a[s][3]),
                  "r"(b0), "r"(b1));
        }
    }
    __syncthreads();   // xh/wh dead; reuse as staging

    // ---- Stage fragments: d[row g(+8)][col j*8 + t*2 (+1)] ----
    const int g  = lane >> 2;
    const int t4 = lane & 3;
    #pragma unroll
    for (int j = 0; j < 16; j++) {
        *reinterpret_cast<__half2*>(&stage[(m0 + g) * ST_STRIDE + j * 8 + t4 * 2]) =
            __floats2half2_rn(acc[j][0], acc[j][1]);
        *reinterpret_cast<__half2*>(&stage[(m0 + g + 8) * ST_STRIDE + j * 8 + t4 * 2]) =
            __floats2half2_rn(acc[j][2], acc[j][3]);
    }
    __syncthreads();

    // ---- Coalesced store: 128 rows x 16 uint4 ----
    for (int f = tid; f < TN * 16; f += 256) {
        const int row = f >> 4, ch = f & 15;
        const uint4 v = *reinterpret_cast<const uint4*>(&stage[row * ST_STRIDE + ch * 8]);
        *reinterpret_cast<uint4*>(xt + (size_t)(base + row) * N_COLS + ch * 8) = v;
    }
}

// ---------------------------------------------------------------------------
// Zero fill (n4 float4 elements).
// ---------------------------------------------------------------------------
__global__ void zero_k(float4* __restrict__ p, int n4)
{
    const int i = blockIdx.x * blockDim.x + threadIdx.x;
    if (i < n4) p[i] = make_float4(0.f, 0.f, 0.f, 0.f);
}

// ---------------------------------------------------------------------------
// Edge scatter: agg_fp16[dst] += xt_fp16[src, etype*32 : +32].
// 2 lanes/edge, each moves 32B (16 halfs) with two red.add.v4.f16x2 (16B each).
// ---------------------------------------------------------------------------
__global__ void __launch_bounds__(256) scatter_k(
    const __half* __restrict__ xt, const int* __restrict__ src,
    const int* __restrict__ dst, const int* __restrict__ et,
    __half* __restrict__ agg, int nedges)
{
    const int t = blockIdx.x * blockDim.x + threadIdx.x;
    const int e = t >> 1;
    if (e >= nedges) return;
    const int q = t & 1;

    const int s = __ldg(src + e);
    const int d = __ldg(dst + e);
    const int r = __ldg(et  + e);

    const __half* gp = xt + (size_t)s * N_COLS + r * N_FEAT + q * 16;
    const uint4 p0 = *reinterpret_cast<const uint4*>(gp);
    const uint4 p1 = *reinterpret_cast<const uint4*>(gp + 8);

    __half* ap = agg + (size_t)d * N_FEAT + q * 16;
    asm volatile("red.global.add.noftz.v4.f16x2 [%0], {%1, %2, %3, %4};"
                 :: "l"(ap), "r"(p0.x), "r"(p0.y), "r"(p0.z), "r"(p0.w)
                 : "memory");
    asm volatile("red.global.add.noftz.v4.f16x2 [%0], {%1, %2, %3, %4};"
                 :: "l"(ap + 8), "r"(p1.x), "r"(p1.y), "r"(p1.z), "r"(p1.w)
                 : "memory");
}

// ---------------------------------------------------------------------------
// Pool: out[g][c] = mean_{i<32} relu(agg2[g*32+i][c] + b[c]).
// ---------------------------------------------------------------------------
__global__ void __launch_bounds__(256) pool_k(
    const __half* __restrict__ agg, const float* __restrict__ b,
    float* __restrict__ out, int nnodes)
{
    const int t = blockIdx.x * blockDim.x + threadIdx.x;
    if (t >= nnodes) return;
    const int c = t & 31;
    const int g = t >> 5;
    const float bc = __ldg(b + c);
    const __half* p = agg + (size_t)g * 32 * N_FEAT + c;
    float s = 0.f;
    #pragma unroll
    for (int i = 0; i < 32; i++)
        s += fmaxf(__half2float(p[i * N_FEAT]) + bc, 0.f);
    out[t] = s * (1.0f / 32.0f);
}

// ---------------------------------------------------------------------------
extern "C" void kernel_launch(void* const* d_in, const int* in_sizes, int n_in,
                              void* d_out, int out_size)
{
    const float* x   = (const float*)d_in[0];
    const int*   src = (const int*)  d_in[1];
    const int*   dst = (const int*)  d_in[2];
    const int*   et  = (const int*)  d_in[3];
    const float* W   = (const float*)d_in[4];
    const float* b   = (const float*)d_in[5];

    const int nnodes = in_sizes[0] / N_FEAT;
    const int nedges = in_sizes[1];

    __half *xt, *agg1, *agg2;
    cudaGetSymbolAddress((void**)&xt,   g_xt);
    cudaGetSymbolAddress((void**)&agg1, g_agg1);
    cudaGetSymbolAddress((void**)&agg2, g_agg2);

    const int tf_blocks = nnodes / TN;
    const int n4        = nnodes * N_FEAT * (int)sizeof(__half) / 16; // agg in float4 units
    const int z_blocks  = (n4 + 255) / 256;
    const int sc_blocks = (nedges * 2 + 255) / 256;

    // Layer 1
    transform_k<false><<<tf_blocks, 256>>>(x, W, b, xt);
    zero_k<<<z_blocks, 256>>>((float4*)agg1, n4);
    scatter_k<<<sc_blocks, 256>>>(xt, src, dst, et, agg1, nedges);

    // Layer 2 (input = relu(agg1 + b), fused into transform)
    transform_k<true><<<tf_blocks, 256>>>(agg1, W, b, xt);
    zero_k<<<z_blocks, 256>>>((float4*)agg2, n4);
    scatter_k<<<sc_blocks, 256>>>(xt, src, dst, et, agg2, nedges);

    // Pool (bias+relu fused)
    pool_k<<<(nnodes + 255) / 256, 256>>>(agg2, b, (float*)d_out, nnodes);
    (void)n_in; (void)out_size;
}